// round 4
// baseline (speedup 1.0000x reference)
#include <cuda_runtime.h>
#include <cuda_bf16.h>

#define BATCH  32
#define LSEQ   1025
#define NTOK   513
#define TLEN   2048
#define EMB    384
#define TT     16            // frames per tile
#define NTILES (TLEN / TT)   // 128
#define NTH    384           // threads per block; each owns 1 embedding col
#define CHMAX  64            // max compacted tokens per tile (worst case ~59)

__device__ float4 g_tok[BATCH][NTOK];   // {center, 1/sig, reach (-1e30 if dropped), token_id bits}
__device__ float  g_cumend[BATCH];
__device__ int    g_wlo[BATCH][NTILES];
__device__ int    g_whi[BATCH][NTILES];

// ---------------- Kernel A: merge + scan + token params + per-tile windows ----------------
__global__ void prep_kernel(const int* __restrict__ text, const int* __restrict__ durs) {
    int b = blockIdx.x;
    int i = threadIdx.x;
    __shared__ float a[NTOK];

    if (i < NTILES) { g_wlo[b][i] = NTOK; g_whi[b][i] = 0; }

    float d = 0.0f; int tx = 0;
    if (i < NTOK) {
        if (i == 0) { d = (float)durs[b * LSEQ]; tx = text[b * LSEQ]; }
        else {
            d  = (float)(durs[b * LSEQ + 2 * i - 1] + durs[b * LSEQ + 2 * i]);
            tx = text[b * LSEQ + 2 * i - 1];
        }
        a[i] = d;
    }
    __syncthreads();
    // Hillis-Steele inclusive scan
    for (int off = 1; off < NTOK; off <<= 1) {
        float v = 0.0f;
        if (i < NTOK) { v = a[i]; if (i >= off) v += a[i - off]; }
        __syncthreads();
        if (i < NTOK) a[i] = v;
        __syncthreads();
    }
    if (i < NTOK) {
        float cum  = a[i];
        float c    = cum - 0.5f * d;
        float sig  = 0.5f * d + 1e-6f;
        float invs = 1.0f / sig;
        bool  kept = (tx != 0) && (d > 0.0f);
        // z-cut = 7: truncated weights < 1.7e-11 << eps=1e-6 in normalizer
        float r = kept ? (3.5f * d + 0.51f) : -1e30f;
        g_tok[b][i] = make_float4(c, invs, r, __int_as_float(tx));
        if (kept) {
            int k0 = max(0, (int)ceilf((c - r - ((float)TT - 0.5f)) * (1.0f / TT)));
            int k1 = min(NTILES - 1, (int)floorf((c + r - 0.5f) * (1.0f / TT)));
            for (int k = k0; k <= k1; ++k) {
                atomicMin(&g_wlo[b][k], i);
                atomicMax(&g_whi[b][k], i + 1);
            }
        }
        if (i == NTOK - 1) g_cumend[b] = cum;
    }
}

// ---------------- Kernel B: windowed gaussian upsample ----------------
__global__ void __launch_bounds__(NTH, 4)
gauss_kernel(const float* __restrict__ emb, float* __restrict__ out) {
    const int b    = blockIdx.y;
    const int tile = blockIdx.x;
    const int t0   = tile * TT;
    const int tid  = threadIdx.x;       // owns embedding column tid

    __shared__ __align__(16) float w_s[CHMAX][TT];
    __shared__ float s_c[CHMAX], s_is[CHMAX], s_cf[CHMAX];
    __shared__ int   s_tok[CHMAX];
    __shared__ float wsum[TT], scale_s[TT];
    __shared__ int   s_cnt;

    if (tid < TT) wsum[tid] = 0.0f;
    if (tid == 0) s_cnt = 0;
    __syncthreads();

    // ---- compact per-token-reach-filtered token list for this tile ----
    const float tlo = (float)t0 + 0.5f;
    const float thi = (float)t0 + (float)TT - 0.5f;
    {
        const int nlo = g_wlo[b][tile];
        const int nhi = g_whi[b][tile];
        for (int n = nlo + tid; n < nhi; n += NTH) {
            float4 p = g_tok[b][n];
            if (p.x - p.z <= thi && p.x + p.z >= tlo) {
                int s = atomicAdd(&s_cnt, 1);
                if (s < CHMAX) {
                    s_c[s]   = p.x;
                    s_is[s]  = p.y;
                    s_cf[s]  = 0.3989422804014327f * p.y;
                    s_tok[s] = __float_as_int(p.w);
                }
            }
        }
    }
    __syncthreads();
    const int cnt = min(s_cnt, CHMAX);

    // ---- phase 1: weights -> smem; per-thread register wsum (frame fixed = tid & 15) ----
    {
        const int   myt = tid & (TT - 1);
        const float tm  = (float)(t0 + myt) + 0.5f;
        float wl = 0.0f;
        for (int idx = tid; idx < cnt * TT; idx += NTH) {
            int nl = idx >> 4;
            float z = (tm - s_c[nl]) * s_is[nl];
            float w = s_cf[nl] * __expf(-0.5f * z * z);
            w_s[nl][myt] = w;
            wl += w;
        }
        atomicAdd(&wsum[myt], wl);
    }
    __syncthreads();

    if (tid < TT) {
        float tmv = (float)(t0 + tid) + 0.5f;
        scale_s[tid] = (tmv < g_cumend[b]) ? (1.0f / (wsum[tid] + 1e-6f)) : 0.0f;
    }

    // ---- phase 2: acc[t] += w[t] * emb[tok][tid] ----
    float acc[TT];
#pragma unroll
    for (int t = 0; t < TT; ++t) acc[t] = 0.0f;

    float ev = (cnt > 0) ? emb[s_tok[0] * EMB + tid] : 0.0f;
    for (int nl = 0; nl < cnt; ++nl) {
        float evn = (nl + 1 < cnt) ? emb[s_tok[nl + 1] * EMB + tid] : 0.0f;
        const float4* wp = reinterpret_cast<const float4*>(w_s[nl]);
#pragma unroll
        for (int j = 0; j < TT / 4; ++j) {
            float4 w4 = wp[j];
            acc[4 * j + 0] += w4.x * ev;
            acc[4 * j + 1] += w4.y * ev;
            acc[4 * j + 2] += w4.z * ev;
            acc[4 * j + 3] += w4.w * ev;
        }
        ev = evn;
    }
    __syncthreads();   // scale_s ready

    // ---- normalize + store (coalesced per frame) ----
    size_t base = ((size_t)(b * TLEN + t0)) * EMB + tid;
#pragma unroll
    for (int tt = 0; tt < TT; ++tt) {
        out[base + (size_t)tt * EMB] = acc[tt] * scale_s[tt];
    }
}

extern "C" void kernel_launch(void* const* d_in, const int* in_sizes, int n_in,
                              void* d_out, int out_size) {
    const int*   text = (const int*)d_in[0];
    const int*   durs = (const int*)d_in[1];
    const float* emb  = (const float*)d_in[2];
    float* out = (float*)d_out;

    prep_kernel<<<BATCH, 544>>>(text, durs);
    dim3 grid(NTILES, BATCH);
    gauss_kernel<<<grid, NTH>>>(emb, out);
}